// round 12
// baseline (speedup 1.0000x reference)
#include <cuda_runtime.h>
#include <cuda_fp16.h>

// ---------------- problem dims ----------------
constexpr int B = 2, D1 = 8, D2 = 16, D3 = 32, D4 = 32, F = 8, H = 16, H2 = 32;
constexpr int NV = B * D1 * D2 * D3 * D4;  // 262144 voxels
constexpr float LRELU = 0.01f;

// ---------------- static scratch ----------------
__device__ unsigned g_actA[(long)NV * 8];         // conv1 input
__device__ unsigned g_actB[(long)NV * 8];         // conv2 input
__device__ unsigned g_actC[(long)NV * 16];        // conv3 input (2 planes)
__device__ float    g_fout[(long)NV * 32];        // conv fp32 output (reused)
// expanded fp16 weights: [slab][dy][cout][44 u32]
__device__ unsigned g_wx1[25 * 5 * 16 * 44];
__device__ unsigned g_wx2[25 * 5 * 32 * 44];
__device__ unsigned g_wx3[50 * 5 * 16 * 44];
__device__ double g_sum[3 * 32];
__device__ double g_ssq[3 * 32];

// ---------------- helpers ----------------
__device__ __forceinline__ unsigned packh2(float a, float b) {
    __half2 h = __floats2half2_rn(a, b);
    return *(unsigned*)&h;
}
__device__ __forceinline__ void mma_f16(float* c, unsigned a0, unsigned a1, unsigned a2, unsigned a3,
                                        unsigned b0, unsigned b1) {
    asm volatile(
        "mma.sync.aligned.m16n8k16.row.col.f32.f16.f16.f32 "
        "{%0,%1,%2,%3},{%4,%5,%6,%7},{%8,%9},{%0,%1,%2,%3};"
        : "+f"(c[0]), "+f"(c[1]), "+f"(c[2]), "+f"(c[3])
        : "r"(a0), "r"(a1), "r"(a2), "r"(a3), "r"(b0), "r"(b1));
}

// ---------------- embed (+ stats zero) : launch position 0 ----------------
__global__ void embed_kernel(const float* __restrict__ x, const float* __restrict__ we,
                             const float* __restrict__ be, unsigned* __restrict__ act,
                             double* __restrict__ sums, double* __restrict__ ssqs) {
    if (blockIdx.x == 0 && threadIdx.x < 96) {
        sums[threadIdx.x] = 0.0;
        ssqs[threadIdx.x] = 0.0;
    }
    __shared__ float sw[F * H];
    __shared__ float sb[H];
    if (threadIdx.x < F * H) sw[threadIdx.x] = we[threadIdx.x];
    if (threadIdx.x < H) sb[threadIdx.x] = be[threadIdx.x];
    __syncthreads();
    int v = blockIdx.x * blockDim.x + threadIdx.x;
    if (v >= NV) return;
    const float4* xp = (const float4*)(x + v * F);
    float4 x0 = xp[0], x1 = xp[1];
    float xf[F] = {x0.x, x0.y, x0.z, x0.w, x1.x, x1.y, x1.z, x1.w};
    float o[H];
#pragma unroll
    for (int h = 0; h < H; h++) {
        float a = sb[h];
#pragma unroll
        for (int f = 0; f < F; f++) a += xf[f] * sw[f * H + h];
        o[h] = a;
    }
    unsigned p[8];
#pragma unroll
    for (int q = 0; q < 8; q++) p[q] = packh2(o[2*q], o[2*q+1]);
    uint4* dst = (uint4*)(act + (long)v * 8);
    dst[0] = make_uint4(p[0], p[1], p[2], p[3]);
    dst[1] = make_uint4(p[4], p[5], p[6], p[7]);
}

// ---------------- merged weight expansion : launch position 1 ----------------
__device__ __forceinline__ void wext_one(const float* __restrict__ W, unsigned* __restrict__ dst,
                                         int COUT, int CINF, int i) {
    int j  = i % 44;
    int co = (i / 44) % COUT;
    int dy = (i / (44 * COUT)) % 5;
    int s  = i / (220 * COUT);
    int g = s / 25, tap = s % 25, dt = tap / 5, dz = tap % 5;
    unsigned val = 0;
    if (j < 40) {
        int dx = j / 8, ci = 2 * (j % 8);
        long base = dt * 125 + dz * 25 + dy * 5 + dx;
        float w0 = W[((long)co * CINF + g * 16 + ci) * 625 + base];
        float w1 = W[((long)co * CINF + g * 16 + ci + 1) * 625 + base];
        val = packh2(w0, w1);
    }
    dst[i] = val;
}

__global__ void wext_all_kernel(const float* __restrict__ W1, const float* __restrict__ W2,
                                const float* __restrict__ W3, unsigned* __restrict__ d1,
                                unsigned* __restrict__ d2, unsigned* __restrict__ d3) {
    int i = blockIdx.x * blockDim.x + threadIdx.x;
    if (i < 88000)       wext_one(W1, d1, 16, 16, i);
    else if (i < 264000) wext_one(W2, d2, 32, 16, i - 88000);
    else if (i < 440000) wext_one(W3, d3, 16, 32, i - 264000);
}

// ---------------- tensor-core 4D conv: fp16 k16, reg-pipelined LDG + smem double buffer,
//                  single barrier per slab, fused BN stats ----------------
template <int COUT, int SLABS>
__global__ void __launch_bounds__(256)
conv_mma_kernel(const unsigned* __restrict__ act, const unsigned* __restrict__ wext,
                const float* __restrict__ bias, float* __restrict__ fout,
                double* __restrict__ gsum, double* __restrict__ gssq) {
    constexpr int NT = COUT / 8;
    constexpr int SA_U32 = 12 * 36 * 12;          // 5184 per buffer
    constexpr int SW_U32 = 5 * COUT * 44;         // per buffer
    constexpr int NW4 = SW_U32 / 4;
    constexpr int NWIT = (NW4 + 255) / 256;       // 1 (COUT=16) or 2 (COUT=32)
    extern __shared__ unsigned smem_u[];
    unsigned* sAb[2] = {smem_u, smem_u + SA_U32};
    unsigned* sWb[2] = {smem_u + 2 * SA_U32, smem_u + 2 * SA_U32 + SW_U32};
    float* s_st = (float*)(smem_u + 2 * SA_U32 + 2 * SW_U32);   // [2*COUT]

    int bi = blockIdx.x;
    int d3b = (bi & 3) * 8;
    int rest = bi >> 2;
    int d2 = rest & 15, d1 = (rest >> 4) & 7, b = rest >> 7;

    int tid = threadIdx.x, lane = tid & 31, wid = tid >> 5;
    int d3r0 = wid >> 1, h = wid & 1;
    int lq = lane >> 2, lr = lane & 3;

    for (int i = tid; i < 2 * COUT; i += 256) s_st[i] = 0.f;

    float acc[2][NT][4];
#pragma unroll
    for (int t = 0; t < 2; t++)
#pragma unroll
        for (int n = 0; n < NT; n++) {
            float b0 = bias[n * 8 + 2 * lr], b1v = bias[n * 8 + 2 * lr + 1];
            acc[t][n][0] = b0; acc[t][n][1] = b1v; acc[t][n][2] = b0; acc[t][n][3] = b1v;
        }

    const uint4* actu4 = (const uint4*)act;
    const uint4* wxu4  = (const uint4*)wext;

    uint4 ra[4];
    uint4 rw[NWIT];

    auto ldg_slab = [&](int s) {
        int g = s / 25, tap = s % 25;
        int dt = tap / 5, dz = tap % 5;
        int d1s = d1 + dt - 2, d2s = d2 + dz - 2;
        bool v12 = ((unsigned)d1s < 8u) && ((unsigned)d2s < 16u);
        int pbase = g * NV;
        int vb = ((b * 8 + d1s) * 16 + d2s) * 1024;
#pragma unroll
        for (int it = 0; it < 4; it++) {
            int i = tid + it * 256;
            ra[it] = make_uint4(0, 0, 0, 0);
            if (i < 864) {
                int q = i & 1, cell = i >> 1;
                int d4p = cell % 36, srow = cell / 36;
                int d3s = d3b + srow - 2;
                if (v12 && (unsigned)d3s < 32u && d4p >= 2 && d4p < 34)
                    ra[it] = actu4[((long)(pbase + vb + d3s * 32 + d4p - 2) << 1) + q];
            }
        }
        const uint4* wsrc = wxu4 + (long)s * NW4;
#pragma unroll
        for (int jt = 0; jt < NWIT; jt++) {
            int j = tid + jt * 256;
            if (j < NW4) rw[jt] = wsrc[j];
        }
    };

    auto sts_slab = [&](int bufi) {
        unsigned* dA = sAb[bufi];
        unsigned* dW = sWb[bufi];
#pragma unroll
        for (int it = 0; it < 4; it++) {
            int i = tid + it * 256;
            if (i < 864) {
                int q = i & 1, cell = i >> 1;
                *(uint4*)(dA + cell * 12 + q * 4) = ra[it];
            }
        }
#pragma unroll
        for (int jt = 0; jt < NWIT; jt++) {
            int j = tid + jt * 256;
            if (j < NW4) ((uint4*)dW)[j] = rw[jt];
        }
    };

    // prologue: slab 0 -> buf0, prefetch slab 1 into regs
    ldg_slab(0);
    sts_slab(0);
    if (SLABS > 1) ldg_slab(1);
    __syncthreads();

    for (int s = 0; s < SLABS; s++) {
        // store slab s+1 (in regs) into the other buffer; prefetch s+2
        if (s + 1 < SLABS) {
            sts_slab((s + 1) & 1);
            if (s + 2 < SLABS) ldg_slab(s + 2);
        }
        const unsigned* sA = sAb[s & 1];
        const unsigned* sW = sWb[s & 1];

#pragma unroll 1
        for (int dy = 0; dy < 5; dy++) {
            int ar0 = ((d3r0 + dy) * 36 + h * 16 + lq) * 12 + lr;   // m-tile0, row lq
            int ar1 = ar0 + 96;                                      // row lq+8
            int br0 = ar0 + 1728;                                    // m-tile1 (+4 d3rows)
            int br1 = br0 + 96;
            int wb = (dy * COUT + lq) * 44 + lr;
#pragma unroll
            for (int kc = 0; kc < 5; kc++) {
                int ko = kc * 12;
                unsigned a00 = sA[ar0 + ko], a01 = sA[ar1 + ko];
                unsigned a02 = sA[ar0 + ko + 4], a03 = sA[ar1 + ko + 4];
                unsigned a10 = sA[br0 + ko], a11 = sA[br1 + ko];
                unsigned a12 = sA[br0 + ko + 4], a13 = sA[br1 + ko + 4];
#pragma unroll
                for (int n = 0; n < NT; n++) {
                    unsigned b0 = sW[wb + n * 352 + kc * 8];
                    unsigned b1 = sW[wb + n * 352 + kc * 8 + 4];
                    mma_f16(acc[0][n], a00, a01, a02, a03, b0, b1);
                    mma_f16(acc[1][n], a10, a11, a12, a13, b0, b1);
                }
            }
        }
        __syncthreads();   // STS(s+1) visible; compute(s) done before buf reuse at s+2
    }

    // epilogue: store fp32 + fused BN stats
    int vox0 = ((b * 8 + d1) * 16 + d2) * 1024 + d3b * 32;
#pragma unroll
    for (int t = 0; t < 2; t++) {
        int d3r = d3r0 + 4 * t;
        long base = (long)(vox0 + d3r * 32 + h * 16 + lq) * COUT + 2 * lr;
#pragma unroll
        for (int n = 0; n < NT; n++) {
            *(float2*)&fout[base + n * 8]            = make_float2(acc[t][n][0], acc[t][n][1]);
            *(float2*)&fout[base + 8 * COUT + n * 8] = make_float2(acc[t][n][2], acc[t][n][3]);
        }
    }
#pragma unroll
    for (int n = 0; n < NT; n++) {
        float s0 = 0.f, s1 = 0.f, q0 = 0.f, q1 = 0.f;
#pragma unroll
        for (int t = 0; t < 2; t++) {
            s0 += acc[t][n][0] + acc[t][n][2];
            s1 += acc[t][n][1] + acc[t][n][3];
            q0 += acc[t][n][0] * acc[t][n][0] + acc[t][n][2] * acc[t][n][2];
            q1 += acc[t][n][1] * acc[t][n][1] + acc[t][n][3] * acc[t][n][3];
        }
#pragma unroll
        for (int off = 16; off >= 4; off >>= 1) {
            s0 += __shfl_down_sync(0xffffffffu, s0, off);
            s1 += __shfl_down_sync(0xffffffffu, s1, off);
            q0 += __shfl_down_sync(0xffffffffu, q0, off);
            q1 += __shfl_down_sync(0xffffffffu, q1, off);
        }
        if (lq == 0) {
            int ch = n * 8 + 2 * lr;
            atomicAdd(&s_st[ch], s0);
            atomicAdd(&s_st[ch + 1], s1);
            atomicAdd(&s_st[COUT + ch], q0);
            atomicAdd(&s_st[COUT + ch + 1], q1);
        }
    }
    __syncthreads();
    if (tid < COUT)          atomicAdd(&gsum[tid], (double)s_st[tid]);
    else if (tid < 2 * COUT) atomicAdd(&gssq[tid - COUT], (double)s_st[tid]);
}

// ---------------- bn apply (+ leaky relu) -> fp16 planes ----------------
template <int C>
__global__ void bn_apply_kernel(const float* __restrict__ fout, const double* __restrict__ sum,
                                const double* __restrict__ ssq, const float* __restrict__ gamma,
                                const float* __restrict__ beta, unsigned* __restrict__ act) {
    constexpr int NPL = C / 16;
    __shared__ float sc[C], sh[C];
    int tid = threadIdx.x;
    if (tid < C) {
        double m   = sum[tid] / (double)NV;
        double var = ssq[tid] / (double)NV - m * m;
        double inv = 1.0 / sqrt(var + 1e-5);
        float s = gamma[tid] * (float)inv;
        sc[tid] = s;
        sh[tid] = beta[tid] - (float)m * s;
    }
    __syncthreads();
    long total  = (long)NV * NPL;
    long stride = (long)gridDim.x * blockDim.x;
    for (long id = blockIdx.x * (long)blockDim.x + tid; id < total; id += stride) {
        int vox = (int)(id % NV);
        int pl  = (int)(id / NV);
        const float4* src = (const float4*)&fout[(long)vox * C + pl * 16];
        float4 v0 = src[0], v1 = src[1], v2 = src[2], v3 = src[3];
        float vv[16] = {v0.x, v0.y, v0.z, v0.w, v1.x, v1.y, v1.z, v1.w,
                        v2.x, v2.y, v2.z, v2.w, v3.x, v3.y, v3.z, v3.w};
        unsigned p[8];
#pragma unroll
        for (int q = 0; q < 8; q++) {
            float r0 = vv[2*q]   * sc[pl*16 + 2*q]   + sh[pl*16 + 2*q];
            float r1 = vv[2*q+1] * sc[pl*16 + 2*q+1] + sh[pl*16 + 2*q+1];
            r0 = fmaxf(r0, LRELU * r0);
            r1 = fmaxf(r1, LRELU * r1);
            p[q] = packh2(r0, r1);
        }
        uint4* dst = (uint4*)&act[((long)pl * NV + vox) * 8];
        dst[0] = make_uint4(p[0], p[1], p[2], p[3]);
        dst[1] = make_uint4(p[4], p[5], p[6], p[7]);
    }
}

// ---------------- fused BN + leaky relu + projection (layer 3) ----------------
__global__ void bnproj_kernel(const float* __restrict__ fout, const double* __restrict__ sum,
                              const double* __restrict__ ssq, const float* __restrict__ gamma,
                              const float* __restrict__ beta, const float* __restrict__ wp,
                              const float* __restrict__ bp, float* __restrict__ out) {
    __shared__ float sc[H], sh[H], sw[H];
    __shared__ float sb;
    int tid = threadIdx.x;
    if (tid < H) {
        double m   = sum[tid] / (double)NV;
        double var = ssq[tid] / (double)NV - m * m;
        double inv = 1.0 / sqrt(var + 1e-5);
        float s = gamma[tid] * (float)inv;
        sc[tid] = s;
        sh[tid] = beta[tid] - (float)m * s;
        sw[tid] = wp[tid];
    }
    if (tid == 0) sb = bp[0];
    __syncthreads();
    int v = blockIdx.x * blockDim.x + tid;
    if (v >= NV) return;
    const float4* src = (const float4*)&fout[(long)v * H];
    float4 v0 = src[0], v1 = src[1], v2 = src[2], v3 = src[3];
    float vv[16] = {v0.x, v0.y, v0.z, v0.w, v1.x, v1.y, v1.z, v1.w,
                    v2.x, v2.y, v2.z, v2.w, v3.x, v3.y, v3.z, v3.w};
    float a = sb;
#pragma unroll
    for (int c = 0; c < H; c++) {
        float r = vv[c] * sc[c] + sh[c];
        r = fmaxf(r, LRELU * r);
        a += r * sw[c];
    }
    out[v] = a;
}

// ---------------- launch ----------------
extern "C" void kernel_launch(void* const* d_in, const int* in_sizes, int n_in,
                              void* d_out, int out_size) {
    const float* x      = (const float*)d_in[0];
    const float* w_emb  = (const float*)d_in[1];
    const float* b_emb  = (const float*)d_in[2];
    const float* W1     = (const float*)d_in[3];
    const float* b1     = (const float*)d_in[4];
    const float* g1     = (const float*)d_in[5];
    const float* be1    = (const float*)d_in[6];
    const float* W2     = (const float*)d_in[7];
    const float* b2     = (const float*)d_in[8];
    const float* g2     = (const float*)d_in[9];
    const float* be2    = (const float*)d_in[10];
    const float* W3     = (const float*)d_in[11];
    const float* b3     = (const float*)d_in[12];
    const float* g3     = (const float*)d_in[13];
    const float* be3    = (const float*)d_in[14];
    const float* w_proj = (const float*)d_in[15];
    const float* b_proj = (const float*)d_in[16];

    unsigned *actA, *actB, *actC, *wx1, *wx2, *wx3;
    float* fout;
    double *sums, *ssqs;
    cudaGetSymbolAddress((void**)&actA, g_actA);
    cudaGetSymbolAddress((void**)&actB, g_actB);
    cudaGetSymbolAddress((void**)&actC, g_actC);
    cudaGetSymbolAddress((void**)&fout, g_fout);
    cudaGetSymbolAddress((void**)&wx1, g_wx1);
    cudaGetSymbolAddress((void**)&wx2, g_wx2);
    cudaGetSymbolAddress((void**)&wx3, g_wx3);
    cudaGetSymbolAddress((void**)&sums, g_sum);
    cudaGetSymbolAddress((void**)&ssqs, g_ssq);

    // smem: 2*A(20736) + 2*W(5*COUT*44*4) + stats
    // conv1/3: 41472 + 28160 + 128 = 69760 ; conv2: 41472 + 56320 + 256 = 98048
    cudaFuncSetAttribute(conv_mma_kernel<16, 25>, cudaFuncAttributeMaxDynamicSharedMemorySize, 69760);
    cudaFuncSetAttribute(conv_mma_kernel<32, 25>, cudaFuncAttributeMaxDynamicSharedMemorySize, 98048);
    cudaFuncSetAttribute(conv_mma_kernel<16, 50>, cudaFuncAttributeMaxDynamicSharedMemorySize, 69760);

    // position 0: embed (+ stats zero)
    embed_kernel<<<NV / 256, 256>>>(x, w_emb, b_emb, actA, sums, ssqs);
    // position 1: merged weight expansion
    wext_all_kernel<<<(440000 + 255) / 256, 256>>>(W1, W2, W3, wx1, wx2, wx3);
    // position 2: conv1  (ncu capture slot)
    conv_mma_kernel<16, 25><<<1024, 256, 69760>>>(actA, wx1, b1, fout, sums + 0, ssqs + 0);
    bn_apply_kernel<16><<<1024, 256>>>(fout, sums + 0, ssqs + 0, g1, be1, actB);

    conv_mma_kernel<32, 25><<<1024, 256, 98048>>>(actB, wx2, b2, fout, sums + 32, ssqs + 32);
    bn_apply_kernel<32><<<2048, 256>>>(fout, sums + 32, ssqs + 32, g2, be2, actC);

    conv_mma_kernel<16, 50><<<1024, 256, 69760>>>(actC, wx3, b3, fout, sums + 64, ssqs + 64);
    bnproj_kernel<<<NV / 256, 256>>>(fout, sums + 64, ssqs + 64, g3, be3, w_proj, b_proj, (float*)d_out);
}

// round 14
// speedup vs baseline: 1.3196x; 1.3196x over previous
#include <cuda_runtime.h>
#include <cuda_fp16.h>

// ---------------- problem dims ----------------
constexpr int B = 2, D1 = 8, D2 = 16, D3 = 32, D4 = 32, F = 8, H = 16, H2 = 32;
constexpr int NV = B * D1 * D2 * D3 * D4;  // 262144 voxels
constexpr float LRELU = 0.01f;

// ---------------- static scratch ----------------
__device__ unsigned g_actA[(long)NV * 8];         // conv1 input
__device__ unsigned g_actB[(long)NV * 8];         // conv2 input
__device__ unsigned g_actC[(long)NV * 16];        // conv3 input (2 planes)
__device__ float    g_fout[(long)NV * 32];        // conv fp32 output (reused)
// expanded fp16 weights: [slab][dy][cout][44 u32]
__device__ unsigned g_wx1[25 * 5 * 16 * 44];
__device__ unsigned g_wx2[25 * 5 * 32 * 44];
__device__ unsigned g_wx3[50 * 5 * 16 * 44];
__device__ double g_sum[3 * 32];
__device__ double g_ssq[3 * 32];

// ---------------- helpers ----------------
__device__ __forceinline__ unsigned packh2(float a, float b) {
    __half2 h = __floats2half2_rn(a, b);
    return *(unsigned*)&h;
}
__device__ __forceinline__ void mma_f16(float* c, unsigned a0, unsigned a1, unsigned a2, unsigned a3,
                                        unsigned b0, unsigned b1) {
    asm volatile(
        "mma.sync.aligned.m16n8k16.row.col.f32.f16.f16.f32 "
        "{%0,%1,%2,%3},{%4,%5,%6,%7},{%8,%9},{%0,%1,%2,%3};"
        : "+f"(c[0]), "+f"(c[1]), "+f"(c[2]), "+f"(c[3])
        : "r"(a0), "r"(a1), "r"(a2), "r"(a3), "r"(b0), "r"(b1));
}

// ---------------- embed : launch position 0 ----------------
__global__ void embed_kernel(const float* __restrict__ x, const float* __restrict__ we,
                             const float* __restrict__ be, unsigned* __restrict__ act) {
    __shared__ float sw[F * H];
    __shared__ float sb[H];
    if (threadIdx.x < F * H) sw[threadIdx.x] = we[threadIdx.x];
    if (threadIdx.x < H) sb[threadIdx.x] = be[threadIdx.x];
    __syncthreads();
    int v = blockIdx.x * blockDim.x + threadIdx.x;
    if (v >= NV) return;
    const float4* xp = (const float4*)(x + v * F);
    float4 x0 = xp[0], x1 = xp[1];
    float xf[F] = {x0.x, x0.y, x0.z, x0.w, x1.x, x1.y, x1.z, x1.w};
    float o[H];
#pragma unroll
    for (int h = 0; h < H; h++) {
        float a = sb[h];
#pragma unroll
        for (int f = 0; f < F; f++) a += xf[f] * sw[f * H + h];
        o[h] = a;
    }
    unsigned p[8];
#pragma unroll
    for (int q = 0; q < 8; q++) p[q] = packh2(o[2*q], o[2*q+1]);
    uint4* dst = (uint4*)(act + (long)v * 8);
    dst[0] = make_uint4(p[0], p[1], p[2], p[3]);
    dst[1] = make_uint4(p[4], p[5], p[6], p[7]);
}

// ---------------- merged weight expansion : launch position 1 ----------------
__device__ __forceinline__ void wext_one(const float* __restrict__ W, unsigned* __restrict__ dst,
                                         int COUT, int CINF, int i) {
    int j  = i % 44;
    int co = (i / 44) % COUT;
    int dy = (i / (44 * COUT)) % 5;
    int s  = i / (220 * COUT);
    int g = s / 25, tap = s % 25, dt = tap / 5, dz = tap % 5;
    unsigned val = 0;
    if (j < 40) {
        int dx = j / 8, ci = 2 * (j % 8);
        long base = dt * 125 + dz * 25 + dy * 5 + dx;
        float w0 = W[((long)co * CINF + g * 16 + ci) * 625 + base];
        float w1 = W[((long)co * CINF + g * 16 + ci + 1) * 625 + base];
        val = packh2(w0, w1);
    }
    dst[i] = val;
}

__global__ void wext_all_kernel(const float* __restrict__ W1, const float* __restrict__ W2,
                                const float* __restrict__ W3, unsigned* __restrict__ d1,
                                unsigned* __restrict__ d2, unsigned* __restrict__ d3) {
    int i = blockIdx.x * blockDim.x + threadIdx.x;
    if (i < 88000)       wext_one(W1, d1, 16, 16, i);
    else if (i < 264000) wext_one(W2, d2, 32, 16, i - 88000);
    else if (i < 440000) wext_one(W3, d3, 16, 32, i - 264000);
}

// ---------------- stats zero : launch position 2 ----------------
__global__ void zero_stats_kernel(double* s, double* q) {
    int i = threadIdx.x;
    if (i < 96) { s[i] = 0.0; q[i] = 0.0; }
}

// ---------------- tensor-core 4D conv (fp16 k16) + register-pipelined staging + fused BN stats ----
// CTA = (b,d1,d2) x 8 d3-rows, M=256 voxels. 8 warps x 2 m16-tiles.
// A smem: [srow12][d4p36] cell = 12 u32 (16 fp16 + pad) -> conflict-free scalar LDS.
// Staging pipeline: regs hold slab s while LDGs for s+1 fly during compute(s).
template <int COUT, int SLABS>
__global__ void __launch_bounds__(256)
conv_mma_kernel(const unsigned* __restrict__ act, const unsigned* __restrict__ wext,
                const float* __restrict__ bias, float* __restrict__ fout,
                double* __restrict__ gsum, double* __restrict__ gssq) {
    constexpr int NT = COUT / 8;
    constexpr int SA_U32 = 12 * 36 * 12;          // 5184
    constexpr int SW_U32 = 5 * COUT * 44;
    constexpr int NW4 = SW_U32 / 4;               // uint4 count of W slab
    constexpr int NWIT = (NW4 + 255) / 256;       // 1 (COUT=16) or 2 (COUT=32)
    extern __shared__ unsigned smem_u[];
    unsigned* sA = smem_u;
    unsigned* sW = smem_u + SA_U32;
    float* s_st  = (float*)(smem_u + SA_U32 + SW_U32);   // [2*COUT]

    int bi = blockIdx.x;
    int d3b = (bi & 3) * 8;
    int rest = bi >> 2;
    int d2 = rest & 15, d1 = (rest >> 4) & 7, b = rest >> 7;

    int tid = threadIdx.x, lane = tid & 31, wid = tid >> 5;
    int d3r0 = wid >> 1, h = wid & 1;
    int lq = lane >> 2, lr = lane & 3;

    for (int i = tid; i < 2 * COUT; i += 256) s_st[i] = 0.f;

    float acc[2][NT][4];
#pragma unroll
    for (int t = 0; t < 2; t++)
#pragma unroll
        for (int n = 0; n < NT; n++) {
            float b0 = bias[n * 8 + 2 * lr], b1v = bias[n * 8 + 2 * lr + 1];
            acc[t][n][0] = b0; acc[t][n][1] = b1v; acc[t][n][2] = b0; acc[t][n][3] = b1v;
        }

    const uint4* actu4 = (const uint4*)act;
    const uint4* wxu4  = (const uint4*)wext;

    uint4 ra[4];
    uint4 rw[NWIT];

    // issue LDGs for slab s into registers
    auto ldg_slab = [&](int s) {
        int g = s / 25, tap = s % 25;
        int dt = tap / 5, dz = tap % 5;
        int d1s = d1 + dt - 2, d2s = d2 + dz - 2;
        bool v12 = ((unsigned)d1s < 8u) && ((unsigned)d2s < 16u);
        int pbase = g * NV;
        int vb = ((b * 8 + d1s) * 16 + d2s) * 1024;
#pragma unroll
        for (int it = 0; it < 4; it++) {
            int i = tid + it * 256;
            ra[it] = make_uint4(0, 0, 0, 0);
            if (i < 864) {
                int q = i & 1, cell = i >> 1;
                int d4p = cell % 36, srow = cell / 36;
                int d3s = d3b + srow - 2;
                if (v12 && (unsigned)d3s < 32u && d4p >= 2 && d4p < 34)
                    ra[it] = actu4[((long)(pbase + vb + d3s * 32 + d4p - 2) << 1) + q];
            }
        }
        const uint4* wsrc = wxu4 + (long)s * NW4;
#pragma unroll
        for (int jt = 0; jt < NWIT; jt++) {
            int j = tid + jt * 256;
            if (j < NW4) rw[jt] = wsrc[j];
        }
    };

    ldg_slab(0);

    for (int s = 0; s < SLABS; s++) {
        __syncthreads();   // previous compute done reading smem
        // STS: registers (slab s) -> smem
#pragma unroll
        for (int it = 0; it < 4; it++) {
            int i = tid + it * 256;
            if (i < 864) {
                int q = i & 1, cell = i >> 1;
                *(uint4*)(sA + cell * 12 + q * 4) = ra[it];
            }
        }
#pragma unroll
        for (int jt = 0; jt < NWIT; jt++) {
            int j = tid + jt * 256;
            if (j < NW4) ((uint4*)sW)[j] = rw[jt];
        }
        // prefetch slab s+1 (lands during compute below)
        if (s + 1 < SLABS) ldg_slab(s + 1);
        __syncthreads();

#pragma unroll 1
        for (int dy = 0; dy < 5; dy++) {
            int ar0 = ((d3r0 + dy) * 36 + h * 16 + lq) * 12 + lr;   // m-tile0, row lq
            int ar1 = ar0 + 96;                                      // row lq+8
            int br0 = ar0 + 1728;                                    // m-tile1 (+4 d3rows)
            int br1 = br0 + 96;
            int wb = (dy * COUT + lq) * 44 + lr;
#pragma unroll
            for (int kc = 0; kc < 5; kc++) {
                int ko = kc * 12;
                unsigned a00 = sA[ar0 + ko], a01 = sA[ar1 + ko];
                unsigned a02 = sA[ar0 + ko + 4], a03 = sA[ar1 + ko + 4];
                unsigned a10 = sA[br0 + ko], a11 = sA[br1 + ko];
                unsigned a12 = sA[br0 + ko + 4], a13 = sA[br1 + ko + 4];
#pragma unroll
                for (int n = 0; n < NT; n++) {
                    unsigned b0 = sW[wb + n * 352 + kc * 8];
                    unsigned b1 = sW[wb + n * 352 + kc * 8 + 4];
                    mma_f16(acc[0][n], a00, a01, a02, a03, b0, b1);
                    mma_f16(acc[1][n], a10, a11, a12, a13, b0, b1);
                }
            }
        }
    }

    // epilogue: store fp32 + fused BN stats
    int vox0 = ((b * 8 + d1) * 16 + d2) * 1024 + d3b * 32;
#pragma unroll
    for (int t = 0; t < 2; t++) {
        int d3r = d3r0 + 4 * t;
        long base = (long)(vox0 + d3r * 32 + h * 16 + lq) * COUT + 2 * lr;
#pragma unroll
        for (int n = 0; n < NT; n++) {
            *(float2*)&fout[base + n * 8]            = make_float2(acc[t][n][0], acc[t][n][1]);
            *(float2*)&fout[base + 8 * COUT + n * 8] = make_float2(acc[t][n][2], acc[t][n][3]);
        }
    }
#pragma unroll
    for (int n = 0; n < NT; n++) {
        float s0 = 0.f, s1 = 0.f, q0 = 0.f, q1 = 0.f;
#pragma unroll
        for (int t = 0; t < 2; t++) {
            s0 += acc[t][n][0] + acc[t][n][2];
            s1 += acc[t][n][1] + acc[t][n][3];
            q0 += acc[t][n][0] * acc[t][n][0] + acc[t][n][2] * acc[t][n][2];
            q1 += acc[t][n][1] * acc[t][n][1] + acc[t][n][3] * acc[t][n][3];
        }
#pragma unroll
        for (int off = 16; off >= 4; off >>= 1) {
            s0 += __shfl_down_sync(0xffffffffu, s0, off);
            s1 += __shfl_down_sync(0xffffffffu, s1, off);
            q0 += __shfl_down_sync(0xffffffffu, q0, off);
            q1 += __shfl_down_sync(0xffffffffu, q1, off);
        }
        if (lq == 0) {
            int ch = n * 8 + 2 * lr;
            atomicAdd(&s_st[ch], s0);
            atomicAdd(&s_st[ch + 1], s1);
            atomicAdd(&s_st[COUT + ch], q0);
            atomicAdd(&s_st[COUT + ch + 1], q1);
        }
    }
    __syncthreads();
    if (tid < COUT)          atomicAdd(&gsum[tid], (double)s_st[tid]);
    else if (tid < 2 * COUT) atomicAdd(&gssq[tid - COUT], (double)s_st[tid]);
}

// ---------------- bn apply (+ leaky relu) -> fp16 planes ----------------
template <int C>
__global__ void bn_apply_kernel(const float* __restrict__ fout, const double* __restrict__ sum,
                                const double* __restrict__ ssq, const float* __restrict__ gamma,
                                const float* __restrict__ beta, unsigned* __restrict__ act) {
    constexpr int NPL = C / 16;
    __shared__ float sc[C], sh[C];
    int tid = threadIdx.x;
    if (tid < C) {
        double m   = sum[tid] / (double)NV;
        double var = ssq[tid] / (double)NV - m * m;
        double inv = 1.0 / sqrt(var + 1e-5);
        float s = gamma[tid] * (float)inv;
        sc[tid] = s;
        sh[tid] = beta[tid] - (float)m * s;
    }
    __syncthreads();
    long total  = (long)NV * NPL;
    long stride = (long)gridDim.x * blockDim.x;
    for (long id = blockIdx.x * (long)blockDim.x + tid; id < total; id += stride) {
        int vox = (int)(id % NV);
        int pl  = (int)(id / NV);
        const float4* src = (const float4*)&fout[(long)vox * C + pl * 16];
        float4 v0 = src[0], v1 = src[1], v2 = src[2], v3 = src[3];
        float vv[16] = {v0.x, v0.y, v0.z, v0.w, v1.x, v1.y, v1.z, v1.w,
                        v2.x, v2.y, v2.z, v2.w, v3.x, v3.y, v3.z, v3.w};
        unsigned p[8];
#pragma unroll
        for (int q = 0; q < 8; q++) {
            float r0 = vv[2*q]   * sc[pl*16 + 2*q]   + sh[pl*16 + 2*q];
            float r1 = vv[2*q+1] * sc[pl*16 + 2*q+1] + sh[pl*16 + 2*q+1];
            r0 = fmaxf(r0, LRELU * r0);
            r1 = fmaxf(r1, LRELU * r1);
            p[q] = packh2(r0, r1);
        }
        uint4* dst = (uint4*)&act[((long)pl * NV + vox) * 8];
        dst[0] = make_uint4(p[0], p[1], p[2], p[3]);
        dst[1] = make_uint4(p[4], p[5], p[6], p[7]);
    }
}

// ---------------- fused BN + leaky relu + projection (layer 3) ----------------
__global__ void bnproj_kernel(const float* __restrict__ fout, const double* __restrict__ sum,
                              const double* __restrict__ ssq, const float* __restrict__ gamma,
                              const float* __restrict__ beta, const float* __restrict__ wp,
                              const float* __restrict__ bp, float* __restrict__ out) {
    __shared__ float sc[H], sh[H], sw[H];
    __shared__ float sb;
    int tid = threadIdx.x;
    if (tid < H) {
        double m   = sum[tid] / (double)NV;
        double var = ssq[tid] / (double)NV - m * m;
        double inv = 1.0 / sqrt(var + 1e-5);
        float s = gamma[tid] * (float)inv;
        sc[tid] = s;
        sh[tid] = beta[tid] - (float)m * s;
        sw[tid] = wp[tid];
    }
    if (tid == 0) sb = bp[0];
    __syncthreads();
    int v = blockIdx.x * blockDim.x + tid;
    if (v >= NV) return;
    const float4* src = (const float4*)&fout[(long)v * H];
    float4 v0 = src[0], v1 = src[1], v2 = src[2], v3 = src[3];
    float vv[16] = {v0.x, v0.y, v0.z, v0.w, v1.x, v1.y, v1.z, v1.w,
                    v2.x, v2.y, v2.z, v2.w, v3.x, v3.y, v3.z, v3.w};
    float a = sb;
#pragma unroll
    for (int c = 0; c < H; c++) {
        float r = vv[c] * sc[c] + sh[c];
        r = fmaxf(r, LRELU * r);
        a += r * sw[c];
    }
    out[v] = a;
}

// ---------------- launch ----------------
extern "C" void kernel_launch(void* const* d_in, const int* in_sizes, int n_in,
                              void* d_out, int out_size) {
    const float* x      = (const float*)d_in[0];
    const float* w_emb  = (const float*)d_in[1];
    const float* b_emb  = (const float*)d_in[2];
    const float* W1     = (const float*)d_in[3];
    const float* b1     = (const float*)d_in[4];
    const float* g1     = (const float*)d_in[5];
    const float* be1    = (const float*)d_in[6];
    const float* W2     = (const float*)d_in[7];
    const float* b2     = (const float*)d_in[8];
    const float* g2     = (const float*)d_in[9];
    const float* be2    = (const float*)d_in[10];
    const float* W3     = (const float*)d_in[11];
    const float* b3     = (const float*)d_in[12];
    const float* g3     = (const float*)d_in[13];
    const float* be3    = (const float*)d_in[14];
    const float* w_proj = (const float*)d_in[15];
    const float* b_proj = (const float*)d_in[16];

    unsigned *actA, *actB, *actC, *wx1, *wx2, *wx3;
    float* fout;
    double *sums, *ssqs;
    cudaGetSymbolAddress((void**)&actA, g_actA);
    cudaGetSymbolAddress((void**)&actB, g_actB);
    cudaGetSymbolAddress((void**)&actC, g_actC);
    cudaGetSymbolAddress((void**)&fout, g_fout);
    cudaGetSymbolAddress((void**)&wx1, g_wx1);
    cudaGetSymbolAddress((void**)&wx2, g_wx2);
    cudaGetSymbolAddress((void**)&wx3, g_wx3);
    cudaGetSymbolAddress((void**)&sums, g_sum);
    cudaGetSymbolAddress((void**)&ssqs, g_ssq);

    // smem: A 20736 + W (5*COUT*44*4) + stats  (single buffer — proven best config)
    cudaFuncSetAttribute(conv_mma_kernel<16, 25>, cudaFuncAttributeMaxDynamicSharedMemorySize, 34944);
    cudaFuncSetAttribute(conv_mma_kernel<32, 25>, cudaFuncAttributeMaxDynamicSharedMemorySize, 49152);
    cudaFuncSetAttribute(conv_mma_kernel<16, 50>, cudaFuncAttributeMaxDynamicSharedMemorySize, 34944);

    // position 0
    embed_kernel<<<NV / 256, 256>>>(x, w_emb, b_emb, actA);
    // position 1
    wext_all_kernel<<<(440000 + 255) / 256, 256>>>(W1, W2, W3, wx1, wx2, wx3);
    // position 2
    zero_stats_kernel<<<1, 128>>>(sums, ssqs);
    // position 3: conv1  (ncu capture slot)
    conv_mma_kernel<16, 25><<<1024, 256, 34944>>>(actA, wx1, b1, fout, sums + 0, ssqs + 0);
    bn_apply_kernel<16><<<1024, 256>>>(fout, sums + 0, ssqs + 0, g1, be1, actB);

    conv_mma_kernel<32, 25><<<1024, 256, 49152>>>(actB, wx2, b2, fout, sums + 32, ssqs + 32);
    bn_apply_kernel<32><<<2048, 256>>>(fout, sums + 32, ssqs + 32, g2, be2, actC);

    conv_mma_kernel<16, 50><<<1024, 256, 34944>>>(actC, wx3, b3, fout, sums + 64, ssqs + 64);
    bnproj_kernel<<<NV / 256, 256>>>(fout, sums + 64, ssqs + 64, g3, be3, w_proj, b_proj, (float*)d_out);
}

// round 15
// speedup vs baseline: 1.4528x; 1.1010x over previous
#include <cuda_runtime.h>
#include <cuda_fp16.h>

// ---------------- problem dims ----------------
constexpr int B = 2, D1 = 8, D2 = 16, D3 = 32, D4 = 32, F = 8, H = 16, H2 = 32;
constexpr int NV = B * D1 * D2 * D3 * D4;  // 262144 voxels
constexpr float LRELU = 0.01f;

// ---------------- static scratch ----------------
__device__ unsigned g_actA[(long)NV * 8];         // conv1 input
__device__ unsigned g_actB[(long)NV * 8];         // conv2 input
__device__ unsigned g_actC[(long)NV * 16];        // conv3 input (2 planes)
__device__ float    g_fout[(long)NV * 32];        // conv fp32 output (reused)
// expanded fp16 weights: [slab][dy][cout][44 u32]
__device__ unsigned g_wx1[25 * 5 * 16 * 44];
__device__ unsigned g_wx2[25 * 5 * 32 * 44];
__device__ unsigned g_wx3[50 * 5 * 16 * 44];
__device__ double g_sum[3 * 32];
__device__ double g_ssq[3 * 32];

// ---------------- helpers ----------------
__device__ __forceinline__ unsigned packh2(float a, float b) {
    __half2 h = __floats2half2_rn(a, b);
    return *(unsigned*)&h;
}
__device__ __forceinline__ void mma_f16(float* c, unsigned a0, unsigned a1, unsigned a2, unsigned a3,
                                        unsigned b0, unsigned b1) {
    asm volatile(
        "mma.sync.aligned.m16n8k16.row.col.f32.f16.f16.f32 "
        "{%0,%1,%2,%3},{%4,%5,%6,%7},{%8,%9},{%0,%1,%2,%3};"
        : "+f"(c[0]), "+f"(c[1]), "+f"(c[2]), "+f"(c[3])
        : "r"(a0), "r"(a1), "r"(a2), "r"(a3), "r"(b0), "r"(b1));
}

// ---------------- embed : launch position 0 ----------------
__global__ void embed_kernel(const float* __restrict__ x, const float* __restrict__ we,
                             const float* __restrict__ be, unsigned* __restrict__ act) {
    __shared__ float sw[F * H];
    __shared__ float sb[H];
    if (threadIdx.x < F * H) sw[threadIdx.x] = we[threadIdx.x];
    if (threadIdx.x < H) sb[threadIdx.x] = be[threadIdx.x];
    __syncthreads();
    int v = blockIdx.x * blockDim.x + threadIdx.x;
    if (v >= NV) return;
    const float4* xp = (const float4*)(x + v * F);
    float4 x0 = xp[0], x1 = xp[1];
    float xf[F] = {x0.x, x0.y, x0.z, x0.w, x1.x, x1.y, x1.z, x1.w};
    float o[H];
#pragma unroll
    for (int h = 0; h < H; h++) {
        float a = sb[h];
#pragma unroll
        for (int f = 0; f < F; f++) a += xf[f] * sw[f * H + h];
        o[h] = a;
    }
    unsigned p[8];
#pragma unroll
    for (int q = 0; q < 8; q++) p[q] = packh2(o[2*q], o[2*q+1]);
    uint4* dst = (uint4*)(act + (long)v * 8);
    dst[0] = make_uint4(p[0], p[1], p[2], p[3]);
    dst[1] = make_uint4(p[4], p[5], p[6], p[7]);
}

// ---------------- merged weight expansion : launch position 1 ----------------
__device__ __forceinline__ void wext_one(const float* __restrict__ W, unsigned* __restrict__ dst,
                                         int COUT, int CINF, int i) {
    int j  = i % 44;
    int co = (i / 44) % COUT;
    int dy = (i / (44 * COUT)) % 5;
    int s  = i / (220 * COUT);
    int g = s / 25, tap = s % 25, dt = tap / 5, dz = tap % 5;
    unsigned val = 0;
    if (j < 40) {
        int dx = j / 8, ci = 2 * (j % 8);
        long base = dt * 125 + dz * 25 + dy * 5 + dx;
        float w0 = W[((long)co * CINF + g * 16 + ci) * 625 + base];
        float w1 = W[((long)co * CINF + g * 16 + ci + 1) * 625 + base];
        val = packh2(w0, w1);
    }
    dst[i] = val;
}

__global__ void wext_all_kernel(const float* __restrict__ W1, const float* __restrict__ W2,
                                const float* __restrict__ W3, unsigned* __restrict__ d1,
                                unsigned* __restrict__ d2, unsigned* __restrict__ d3) {
    int i = blockIdx.x * blockDim.x + threadIdx.x;
    if (i < 88000)       wext_one(W1, d1, 16, 16, i);
    else if (i < 264000) wext_one(W2, d2, 32, 16, i - 88000);
    else if (i < 440000) wext_one(W3, d3, 16, 32, i - 264000);
}

// ---------------- stats zero : launch position 2 ----------------
__global__ void zero_stats_kernel(double* s, double* q) {
    int i = threadIdx.x;
    if (i < 96) { s[i] = 0.0; q[i] = 0.0; }
}

// ---------------- tensor-core 4D conv: weights-as-A (reused), voxels-as-B ----------------
// CTA = (b,d1,d2) x 8 d3-rows = 256 voxels, 128 threads = 4 warps.
// Warp w owns 64 voxels (2 d3-rows): 8 n8-tiles. A (weights m16) loaded once per (dy,dx),
// reused across all 8 voxel tiles -> LDS/mma 2.5 (COUT16) / 1.5 (COUT32).
// A smem: [srow12][d4p36] cell = 12 u32 (16 fp16 + pad) -> conflict-free scalar LDS.
// Register-pipelined staging (proven round-11 pattern, 128-thread variant).
template <int COUT, int SLABS>
__global__ void __launch_bounds__(128)
conv_mma_kernel(const unsigned* __restrict__ act, const unsigned* __restrict__ wext,
                const float* __restrict__ bias, float* __restrict__ fout,
                double* __restrict__ gsum, double* __restrict__ gssq) {
    constexpr int NCO = COUT / 16;                // A m16-tiles (1 or 2)
    constexpr int SA_U32 = 12 * 36 * 12;          // 5184
    constexpr int SW_U32 = 5 * COUT * 44;
    constexpr int NW4 = SW_U32 / 4;               // uint4 count of W slab (220 / 440)
    constexpr int NWIT = (NW4 + 127) / 128;       // 2 or 4
    extern __shared__ unsigned smem_u[];
    unsigned* sA = smem_u;
    unsigned* sW = smem_u + SA_U32;
    float* s_st  = (float*)(smem_u + SA_U32 + SW_U32);   // [2*COUT]

    int bi = blockIdx.x;
    int d3b = (bi & 3) * 8;
    int rest = bi >> 2;
    int d2 = rest & 15, d1 = (rest >> 4) & 7, b = rest >> 7;

    int tid = threadIdx.x, lane = tid & 31, wid = tid >> 5;
    int lq = lane >> 2, lr = lane & 3;
    int d3rbase = wid * 2;                        // warp's first d3-row (of 8)

    for (int i = tid; i < 2 * COUT; i += 128) s_st[i] = 0.f;

    // acc[t][n][4]: t = vox n8-tile (0..7), n = cout m16-tile
    float acc[8][NCO][4];
#pragma unroll
    for (int t = 0; t < 8; t++)
#pragma unroll
        for (int n = 0; n < NCO; n++) {
            float b0 = bias[n * 16 + lq], b1v = bias[n * 16 + lq + 8];
            acc[t][n][0] = b0; acc[t][n][1] = b0;
            acc[t][n][2] = b1v; acc[t][n][3] = b1v;
        }

    const uint4* actu4 = (const uint4*)act;
    const uint4* wxu4  = (const uint4*)wext;

    uint4 ra[7];
    uint4 rw[NWIT];

    auto ldg_slab = [&](int s) {
        int g = s / 25, tap = s % 25;
        int dt = tap / 5, dz = tap % 5;
        int d1s = d1 + dt - 2, d2s = d2 + dz - 2;
        bool v12 = ((unsigned)d1s < 8u) && ((unsigned)d2s < 16u);
        int pbase = g * NV;
        int vb = ((b * 8 + d1s) * 16 + d2s) * 1024;
#pragma unroll
        for (int it = 0; it < 7; it++) {
            int i = tid + it * 128;
            ra[it] = make_uint4(0, 0, 0, 0);
            if (i < 864) {
                int q = i & 1, cell = i >> 1;
                int d4p = cell % 36, srow = cell / 36;
                int d3s = d3b + srow - 2;
                if (v12 && (unsigned)d3s < 32u && d4p >= 2 && d4p < 34)
                    ra[it] = actu4[((long)(pbase + vb + d3s * 32 + d4p - 2) << 1) + q];
            }
        }
        const uint4* wsrc = wxu4 + (long)s * NW4;
#pragma unroll
        for (int jt = 0; jt < NWIT; jt++) {
            int j = tid + jt * 128;
            if (j < NW4) rw[jt] = wsrc[j];
        }
    };

    ldg_slab(0);

    for (int s = 0; s < SLABS; s++) {
        __syncthreads();   // previous compute done reading smem
#pragma unroll
        for (int it = 0; it < 7; it++) {
            int i = tid + it * 128;
            if (i < 864) {
                int q = i & 1, cell = i >> 1;
                *(uint4*)(sA + cell * 12 + q * 4) = ra[it];
            }
        }
#pragma unroll
        for (int jt = 0; jt < NWIT; jt++) {
            int j = tid + jt * 128;
            if (j < NW4) ((uint4*)sW)[j] = rw[jt];
        }
        if (s + 1 < SLABS) ldg_slab(s + 1);
        __syncthreads();

#pragma unroll 1
        for (int dy = 0; dy < 5; dy++) {
#pragma unroll
            for (int dx = 0; dx < 5; dx++) {
                // A = weights m16k16 per cout-tile (reused across all 8 voxel tiles)
                unsigned a0[NCO], a1[NCO], a2[NCO], a3[NCO];
#pragma unroll
                for (int n = 0; n < NCO; n++) {
                    int w0 = (dy * COUT + n * 16 + lq) * 44 + dx * 8 + lr;
                    int w1 = (dy * COUT + n * 16 + lq + 8) * 44 + dx * 8 + lr;
                    a0[n] = sW[w0];
                    a2[n] = sW[w0 + 4];
                    a1[n] = sW[w1];
                    a3[n] = sW[w1 + 4];
                }
                int crow0 = (d3rbase + dy) * 36 + lq + dx;   // t>>2 == 0
#pragma unroll
                for (int t = 0; t < 8; t++) {
                    int cell = crow0 + ((t >> 2) * 36) + (t & 3) * 8;
                    unsigned b0 = sA[cell * 12 + lr];
                    unsigned b1 = sA[cell * 12 + lr + 4];
#pragma unroll
                    for (int n = 0; n < NCO; n++)
                        mma_f16(acc[t][n], a0[n], a1[n], a2[n], a3[n], b0, b1);
                }
            }
        }
    }

    // epilogue: C fragment rows = couts (lq, lq+8), cols = vox (2lr, 2lr+1)
    int vox0 = ((b * 8 + d1) * 16 + d2) * 1024 + d3b * 32 + wid * 64;
#pragma unroll
    for (int t = 0; t < 8; t++) {
        int voxt = vox0 + (t >> 2) * 32 + (t & 3) * 8 + 2 * lr;
#pragma unroll
        for (int n = 0; n < NCO; n++) {
            int c0 = n * 16 + lq;
            long base = (long)voxt * COUT;
            fout[base + c0]            = acc[t][n][0];
            fout[base + COUT + c0]     = acc[t][n][1];
            fout[base + c0 + 8]        = acc[t][n][2];
            fout[base + COUT + c0 + 8] = acc[t][n][3];
        }
    }
    // fused BN stats: per lane, cout lq (c0+c1) and cout lq+8 (c2+c3), reduce over lr (vox)
#pragma unroll
    for (int n = 0; n < NCO; n++) {
        float s0 = 0.f, s1 = 0.f, q0 = 0.f, q1 = 0.f;
#pragma unroll
        for (int t = 0; t < 8; t++) {
            s0 += acc[t][n][0] + acc[t][n][1];
            s1 += acc[t][n][2] + acc[t][n][3];
            q0 += acc[t][n][0] * acc[t][n][0] + acc[t][n][1] * acc[t][n][1];
            q1 += acc[t][n][2] * acc[t][n][2] + acc[t][n][3] * acc[t][n][3];
        }
        // reduce over the 4 lanes of each lq group (lr = 0..3)
#pragma unroll
        for (int off = 2; off >= 1; off >>= 1) {
            s0 += __shfl_down_sync(0xffffffffu, s0, off);
            s1 += __shfl_down_sync(0xffffffffu, s1, off);
            q0 += __shfl_down_sync(0xffffffffu, q0, off);
            q1 += __shfl_down_sync(0xffffffffu, q1, off);
        }
        if (lr == 0) {
            atomicAdd(&s_st[n * 16 + lq], s0);
            atomicAdd(&s_st[n * 16 + lq + 8], s1);
            atomicAdd(&s_st[COUT + n * 16 + lq], q0);
            atomicAdd(&s_st[COUT + n * 16 + lq + 8], q1);
        }
    }
    __syncthreads();
    if (tid < COUT)          atomicAdd(&gsum[tid], (double)s_st[tid]);
    else if (tid < 2 * COUT) atomicAdd(&gssq[tid - COUT], (double)s_st[tid]);
}

// ---------------- bn apply (+ leaky relu) -> fp16 planes ----------------
template <int C>
__global__ void bn_apply_kernel(const float* __restrict__ fout, const double* __restrict__ sum,
                                const double* __restrict__ ssq, const float* __restrict__ gamma,
                                const float* __restrict__ beta, unsigned* __restrict__ act) {
    constexpr int NPL = C / 16;
    __shared__ float sc[C], sh[C];
    int tid = threadIdx.x;
    if (tid < C) {
        double m   = sum[tid] / (double)NV;
        double var = ssq[tid] / (double)NV - m * m;
        double inv = 1.0 / sqrt(var + 1e-5);
        float s = gamma[tid] * (float)inv;
        sc[tid] = s;
        sh[tid] = beta[tid] - (float)m * s;
    }
    __syncthreads();
    long total  = (long)NV * NPL;
    long stride = (long)gridDim.x * blockDim.x;
    for (long id = blockIdx.x * (long)blockDim.x + tid; id < total; id += stride) {
        int vox = (int)(id % NV);
        int pl  = (int)(id / NV);
        const float4* src = (const float4*)&fout[(long)vox * C + pl * 16];
        float4 v0 = src[0], v1 = src[1], v2 = src[2], v3 = src[3];
        float vv[16] = {v0.x, v0.y, v0.z, v0.w, v1.x, v1.y, v1.z, v1.w,
                        v2.x, v2.y, v2.z, v2.w, v3.x, v3.y, v3.z, v3.w};
        unsigned p[8];
#pragma unroll
        for (int q = 0; q < 8; q++) {
            float r0 = vv[2*q]   * sc[pl*16 + 2*q]   + sh[pl*16 + 2*q];
            float r1 = vv[2*q+1] * sc[pl*16 + 2*q+1] + sh[pl*16 + 2*q+1];
            r0 = fmaxf(r0, LRELU * r0);
            r1 = fmaxf(r1, LRELU * r1);
            p[q] = packh2(r0, r1);
        }
        uint4* dst = (uint4*)&act[((long)pl * NV + vox) * 8];
        dst[0] = make_uint4(p[0], p[1], p[2], p[3]);
        dst[1] = make_uint4(p[4], p[5], p[6], p[7]);
    }
}

// ---------------- fused BN + leaky relu + projection (layer 3) ----------------
__global__ void bnproj_kernel(const float* __restrict__ fout, const double* __restrict__ sum,
                              const double* __restrict__ ssq, const float* __restrict__ gamma,
                              const float* __restrict__ beta, const float* __restrict__ wp,
                              const float* __restrict__ bp, float* __restrict__ out) {
    __shared__ float sc[H], sh[H], sw[H];
    __shared__ float sb;
    int tid = threadIdx.x;
    if (tid < H) {
        double m   = sum[tid] / (double)NV;
        double var = ssq[tid] / (double)NV - m * m;
        double inv = 1.0 / sqrt(var + 1e-5);
        float s = gamma[tid] * (float)inv;
        sc[tid] = s;
        sh[tid] = beta[tid] - (float)m * s;
        sw[tid] = wp[tid];
    }
    if (tid == 0) sb = bp[0];
    __syncthreads();
    int v = blockIdx.x * blockDim.x + tid;
    if (v >= NV) return;
    const float4* src = (const float4*)&fout[(long)v * H];
    float4 v0 = src[0], v1 = src[1], v2 = src[2], v3 = src[3];
    float vv[16] = {v0.x, v0.y, v0.z, v0.w, v1.x, v1.y, v1.z, v1.w,
                    v2.x, v2.y, v2.z, v2.w, v3.x, v3.y, v3.z, v3.w};
    float a = sb;
#pragma unroll
    for (int c = 0; c < H; c++) {
        float r = vv[c] * sc[c] + sh[c];
        r = fmaxf(r, LRELU * r);
        a += r * sw[c];
    }
    out[v] = a;
}

// ---------------- launch ----------------
extern "C" void kernel_launch(void* const* d_in, const int* in_sizes, int n_in,
                              void* d_out, int out_size) {
    const float* x      = (const float*)d_in[0];
    const float* w_emb  = (const float*)d_in[1];
    const float* b_emb  = (const float*)d_in[2];
    const float* W1     = (const float*)d_in[3];
    const float* b1     = (const float*)d_in[4];
    const float* g1     = (const float*)d_in[5];
    const float* be1    = (const float*)d_in[6];
    const float* W2     = (const float*)d_in[7];
    const float* b2     = (const float*)d_in[8];
    const float* g2     = (const float*)d_in[9];
    const float* be2    = (const float*)d_in[10];
    const float* W3     = (const float*)d_in[11];
    const float* b3     = (const float*)d_in[12];
    const float* g3     = (const float*)d_in[13];
    const float* be3    = (const float*)d_in[14];
    const float* w_proj = (const float*)d_in[15];
    const float* b_proj = (const float*)d_in[16];

    unsigned *actA, *actB, *actC, *wx1, *wx2, *wx3;
    float* fout;
    double *sums, *ssqs;
    cudaGetSymbolAddress((void**)&actA, g_actA);
    cudaGetSymbolAddress((void**)&actB, g_actB);
    cudaGetSymbolAddress((void**)&actC, g_actC);
    cudaGetSymbolAddress((void**)&fout, g_fout);
    cudaGetSymbolAddress((void**)&wx1, g_wx1);
    cudaGetSymbolAddress((void**)&wx2, g_wx2);
    cudaGetSymbolAddress((void**)&wx3, g_wx3);
    cudaGetSymbolAddress((void**)&sums, g_sum);
    cudaGetSymbolAddress((void**)&ssqs, g_ssq);

    // smem: A 20736 + W (5*COUT*44*4) + stats  (same sizes as proven config)
    cudaFuncSetAttribute(conv_mma_kernel<16, 25>, cudaFuncAttributeMaxDynamicSharedMemorySize, 34944);
    cudaFuncSetAttribute(conv_mma_kernel<32, 25>, cudaFuncAttributeMaxDynamicSharedMemorySize, 49152);
    cudaFuncSetAttribute(conv_mma_kernel<16, 50>, cudaFuncAttributeMaxDynamicSharedMemorySize, 34944);

    // position 0
    embed_kernel<<<NV / 256, 256>>>(x, w_emb, b_emb, actA);
    // position 1
    wext_all_kernel<<<(440000 + 255) / 256, 256>>>(W1, W2, W3, wx1, wx2, wx3);
    // position 2
    zero_stats_kernel<<<1, 128>>>(sums, ssqs);
    // position 3: conv1  (ncu capture slot)
    conv_mma_kernel<16, 25><<<1024, 128, 34944>>>(actA, wx1, b1, fout, sums + 0, ssqs + 0);
    bn_apply_kernel<16><<<1024, 256>>>(fout, sums + 0, ssqs + 0, g1, be1, actB);

    conv_mma_kernel<32, 25><<<1024, 128, 49152>>>(actB, wx2, b2, fout, sums + 32, ssqs + 32);
    bn_apply_kernel<32><<<2048, 256>>>(fout, sums + 32, ssqs + 32, g2, be2, actC);

    conv_mma_kernel<16, 50><<<1024, 128, 34944>>>(actC, wx3, b3, fout, sums + 64, ssqs + 64);
    bnproj_kernel<<<NV / 256, 256>>>(fout, sums + 64, ssqs + 64, g3, be3, w_proj, b_proj, (float*)d_out);
}

// round 16
// speedup vs baseline: 1.6123x; 1.1098x over previous
#include <cuda_runtime.h>
#include <cuda_fp16.h>

// ---------------- problem dims ----------------
constexpr int B = 2, D1 = 8, D2 = 16, D3 = 32, D4 = 32, F = 8, H = 16, H2 = 32;
constexpr int NV = B * D1 * D2 * D3 * D4;  // 262144 voxels
constexpr float LRELU = 0.01f;

// ---------------- static scratch ----------------
__device__ unsigned g_actA[(long)NV * 8];         // conv1 input
__device__ unsigned g_actB[(long)NV * 8];         // conv2 input
__device__ unsigned g_actC[(long)NV * 16];        // conv3 input (2 planes)
__device__ float    g_fout[(long)NV * 32];        // conv fp32 output (reused)
// expanded fp16 weights: [slab][dy][cout][44 u32]
__device__ unsigned g_wx1[25 * 5 * 16 * 44];
__device__ unsigned g_wx2[25 * 5 * 32 * 44];
__device__ unsigned g_wx3[50 * 5 * 16 * 44];
__device__ double g_sum[3 * 32];
__device__ double g_ssq[3 * 32];

// ---------------- helpers ----------------
__device__ __forceinline__ unsigned packh2(float a, float b) {
    __half2 h = __floats2half2_rn(a, b);
    return *(unsigned*)&h;
}
__device__ __forceinline__ void mma_f16(float* c, unsigned a0, unsigned a1, unsigned a2, unsigned a3,
                                        unsigned b0, unsigned b1) {
    asm volatile(
        "mma.sync.aligned.m16n8k16.row.col.f32.f16.f16.f32 "
        "{%0,%1,%2,%3},{%4,%5,%6,%7},{%8,%9},{%0,%1,%2,%3};"
        : "+f"(c[0]), "+f"(c[1]), "+f"(c[2]), "+f"(c[3])
        : "r"(a0), "r"(a1), "r"(a2), "r"(a3), "r"(b0), "r"(b1));
}

// ---------------- embed : launch position 0 ----------------
__global__ void embed_kernel(const float* __restrict__ x, const float* __restrict__ we,
                             const float* __restrict__ be, unsigned* __restrict__ act) {
    __shared__ float sw[F * H];
    __shared__ float sb[H];
    if (threadIdx.x < F * H) sw[threadIdx.x] = we[threadIdx.x];
    if (threadIdx.x < H) sb[threadIdx.x] = be[threadIdx.x];
    __syncthreads();
    int v = blockIdx.x * blockDim.x + threadIdx.x;
    if (v >= NV) return;
    const float4* xp = (const float4*)(x + v * F);
    float4 x0 = xp[0], x1 = xp[1];
    float xf[F] = {x0.x, x0.y, x0.z, x0.w, x1.x, x1.y, x1.z, x1.w};
    float o[H];
#pragma unroll
    for (int h = 0; h < H; h++) {
        float a = sb[h];
#pragma unroll
        for (int f = 0; f < F; f++) a += xf[f] * sw[f * H + h];
        o[h] = a;
    }
    unsigned p[8];
#pragma unroll
    for (int q = 0; q < 8; q++) p[q] = packh2(o[2*q], o[2*q+1]);
    uint4* dst = (uint4*)(act + (long)v * 8);
    dst[0] = make_uint4(p[0], p[1], p[2], p[3]);
    dst[1] = make_uint4(p[4], p[5], p[6], p[7]);
}

// ---------------- merged weight expansion : launch position 1 ----------------
__device__ __forceinline__ void wext_one(const float* __restrict__ W, unsigned* __restrict__ dst,
                                         int COUT, int CINF, int i) {
    int j  = i % 44;
    int co = (i / 44) % COUT;
    int dy = (i / (44 * COUT)) % 5;
    int s  = i / (220 * COUT);
    int g = s / 25, tap = s % 25, dt = tap / 5, dz = tap % 5;
    unsigned val = 0;
    if (j < 40) {
        int dx = j / 8, ci = 2 * (j % 8);
        long base = dt * 125 + dz * 25 + dy * 5 + dx;
        float w0 = W[((long)co * CINF + g * 16 + ci) * 625 + base];
        float w1 = W[((long)co * CINF + g * 16 + ci + 1) * 625 + base];
        val = packh2(w0, w1);
    }
    dst[i] = val;
}

__global__ void wext_all_kernel(const float* __restrict__ W1, const float* __restrict__ W2,
                                const float* __restrict__ W3, unsigned* __restrict__ d1,
                                unsigned* __restrict__ d2, unsigned* __restrict__ d3) {
    int i = blockIdx.x * blockDim.x + threadIdx.x;
    if (i < 88000)       wext_one(W1, d1, 16, 16, i);
    else if (i < 264000) wext_one(W2, d2, 32, 16, i - 88000);
    else if (i < 440000) wext_one(W3, d3, 16, 32, i - 264000);
}

// ---------------- stats zero : launch position 2 ----------------
__global__ void zero_stats_kernel(double* s, double* q) {
    int i = threadIdx.x;
    if (i < 96) { s[i] = 0.0; q[i] = 0.0; }
}

// ---------------- tensor-core 4D conv: weights-as-A, voxels-as-B, dy-overlap B hoisting ----
// CTA = (b,d1,d2) x 8 d3-rows = 256 voxels, 128 threads = 4 warps.
// dx-outer loop: hoist 6 rows x 4 colgroups of B fragments (48 regs) once per dx,
// reuse across 5 dy x 8 voxel tiles -> B LDS per slab 400 -> 240 per warp.
template <int COUT, int SLABS>
__global__ void __launch_bounds__(128)
conv_mma_kernel(const unsigned* __restrict__ act, const unsigned* __restrict__ wext,
                const float* __restrict__ bias, float* __restrict__ fout,
                double* __restrict__ gsum, double* __restrict__ gssq) {
    constexpr int NCO = COUT / 16;                // A m16-tiles (1 or 2)
    constexpr int SA_U32 = 12 * 36 * 12;          // 5184
    constexpr int SW_U32 = 5 * COUT * 44;
    constexpr int NW4 = SW_U32 / 4;               // 220 / 440
    constexpr int NWIT = (NW4 + 127) / 128;       // 2 or 4
    extern __shared__ unsigned smem_u[];
    unsigned* sA = smem_u;
    unsigned* sW = smem_u + SA_U32;
    float* s_st  = (float*)(smem_u + SA_U32 + SW_U32);   // [2*COUT]

    int bi = blockIdx.x;
    int d3b = (bi & 3) * 8;
    int rest = bi >> 2;
    int d2 = rest & 15, d1 = (rest >> 4) & 7, b = rest >> 7;

    int tid = threadIdx.x, lane = tid & 31, wid = tid >> 5;
    int lq = lane >> 2, lr = lane & 3;
    int d3rbase = wid * 2;                        // warp's first d3-row (of 8)

    for (int i = tid; i < 2 * COUT; i += 128) s_st[i] = 0.f;

    // acc[t][n][4]: t = vox n8-tile (0..7), n = cout m16-tile
    float acc[8][NCO][4];
#pragma unroll
    for (int t = 0; t < 8; t++)
#pragma unroll
        for (int n = 0; n < NCO; n++) {
            float b0 = bias[n * 16 + lq], b1v = bias[n * 16 + lq + 8];
            acc[t][n][0] = b0; acc[t][n][1] = b0;
            acc[t][n][2] = b1v; acc[t][n][3] = b1v;
        }

    const uint4* actu4 = (const uint4*)act;
    const uint4* wxu4  = (const uint4*)wext;

    uint4 ra[7];
    uint4 rw[NWIT];

    auto ldg_slab = [&](int s) {
        int g = s / 25, tap = s % 25;
        int dt = tap / 5, dz = tap % 5;
        int d1s = d1 + dt - 2, d2s = d2 + dz - 2;
        bool v12 = ((unsigned)d1s < 8u) && ((unsigned)d2s < 16u);
        int pbase = g * NV;
        int vb = ((b * 8 + d1s) * 16 + d2s) * 1024;
#pragma unroll
        for (int it = 0; it < 7; it++) {
            int i = tid + it * 128;
            ra[it] = make_uint4(0, 0, 0, 0);
            if (i < 864) {
                int q = i & 1, cell = i >> 1;
                int d4p = cell % 36, srow = cell / 36;
                int d3s = d3b + srow - 2;
                if (v12 && (unsigned)d3s < 32u && d4p >= 2 && d4p < 34)
                    ra[it] = actu4[((long)(pbase + vb + d3s * 32 + d4p - 2) << 1) + q];
            }
        }
        const uint4* wsrc = wxu4 + (long)s * NW4;
#pragma unroll
        for (int jt = 0; jt < NWIT; jt++) {
            int j = tid + jt * 128;
            if (j < NW4) rw[jt] = wsrc[j];
        }
    };

    ldg_slab(0);

    for (int s = 0; s < SLABS; s++) {
        __syncthreads();   // previous compute done reading smem
#pragma unroll
        for (int it = 0; it < 7; it++) {
            int i = tid + it * 128;
            if (i < 864) {
                int q = i & 1, cell = i >> 1;
                *(uint4*)(sA + cell * 12 + q * 4) = ra[it];
            }
        }
#pragma unroll
        for (int jt = 0; jt < NWIT; jt++) {
            int j = tid + jt * 128;
            if (j < NW4) ((uint4*)sW)[j] = rw[jt];
        }
        if (s + 1 < SLABS) ldg_slab(s + 1);
        __syncthreads();

#pragma unroll 1
        for (int dx = 0; dx < 5; dx++) {
            // hoist B fragments: 6 rows x 4 colgroups x 2 regs, reused across dy and t
            unsigned br[6][4][2];
#pragma unroll
            for (int r = 0; r < 6; r++)
#pragma unroll
                for (int g = 0; g < 4; g++) {
                    int cell = (d3rbase + r) * 36 + lq + dx + g * 8;
                    br[r][g][0] = sA[cell * 12 + lr];
                    br[r][g][1] = sA[cell * 12 + lr + 4];
                }
#pragma unroll
            for (int dy = 0; dy < 5; dy++) {
                unsigned a0[NCO], a1[NCO], a2[NCO], a3[NCO];
#pragma unroll
                for (int n = 0; n < NCO; n++) {
                    int w0 = (dy * COUT + n * 16 + lq) * 44 + dx * 8 + lr;
                    int w1 = (dy * COUT + n * 16 + lq + 8) * 44 + dx * 8 + lr;
                    a0[n] = sW[w0];
                    a2[n] = sW[w0 + 4];
                    a1[n] = sW[w1];
                    a3[n] = sW[w1 + 4];
                }
#pragma unroll
                for (int t = 0; t < 8; t++) {
                    unsigned b0 = br[dy + (t >> 2)][t & 3][0];
                    unsigned b1 = br[dy + (t >> 2)][t & 3][1];
#pragma unroll
                    for (int n = 0; n < NCO; n++)
                        mma_f16(acc[t][n], a0[n], a1[n], a2[n], a3[n], b0, b1);
                }
            }
        }
    }

    // epilogue: C fragment rows = couts (lq, lq+8), cols = vox (2lr, 2lr+1)
    int vox0 = ((b * 8 + d1) * 16 + d2) * 1024 + d3b * 32 + wid * 64;
#pragma unroll
    for (int t = 0; t < 8; t++) {
        int voxt = vox0 + (t >> 2) * 32 + (t & 3) * 8 + 2 * lr;
#pragma unroll
        for (int n = 0; n < NCO; n++) {
            int c0 = n * 16 + lq;
            long base = (long)voxt * COUT;
            fout[base + c0]            = acc[t][n][0];
            fout[base + COUT + c0]     = acc[t][n][1];
            fout[base + c0 + 8]        = acc[t][n][2];
            fout[base + COUT + c0 + 8] = acc[t][n][3];
        }
    }
    // fused BN stats
#pragma unroll
    for (int n = 0; n < NCO; n++) {
        float s0 = 0.f, s1 = 0.f, q0 = 0.f, q1 = 0.f;
#pragma unroll
        for (int t = 0; t < 8; t++) {
            s0 += acc[t][n][0] + acc[t][n][1];
            s1 += acc[t][n][2] + acc[t][n][3];
            q0 += acc[t][n][0] * acc[t][n][0] + acc[t][n][1] * acc[t][n][1];
            q1 += acc[t][n][2] * acc[t][n][2] + acc[t][n][3] * acc[t][n][3];
        }
#pragma unroll
        for (int off = 2; off >= 1; off >>= 1) {
            s0 += __shfl_down_sync(0xffffffffu, s0, off);
            s1 += __shfl_down_sync(0xffffffffu, s1, off);
            q0 += __shfl_down_sync(0xffffffffu, q0, off);
            q1 += __shfl_down_sync(0xffffffffu, q1, off);
        }
        if (lr == 0) {
            atomicAdd(&s_st[n * 16 + lq], s0);
            atomicAdd(&s_st[n * 16 + lq + 8], s1);
            atomicAdd(&s_st[COUT + n * 16 + lq], q0);
            atomicAdd(&s_st[COUT + n * 16 + lq + 8], q1);
        }
    }
    __syncthreads();
    if (tid < COUT)          atomicAdd(&gsum[tid], (double)s_st[tid]);
    else if (tid < 2 * COUT) atomicAdd(&gssq[tid - COUT], (double)s_st[tid]);
}

// ---------------- bn apply (+ leaky relu) -> fp16 planes ----------------
template <int C>
__global__ void bn_apply_kernel(const float* __restrict__ fout, const double* __restrict__ sum,
                                const double* __restrict__ ssq, const float* __restrict__ gamma,
                                const float* __restrict__ beta, unsigned* __restrict__ act) {
    constexpr int NPL = C / 16;
    __shared__ float sc[C], sh[C];
    int tid = threadIdx.x;
    if (tid < C) {
        double m   = sum[tid] / (double)NV;
        double var = ssq[tid] / (double)NV - m * m;
        double inv = 1.0 / sqrt(var + 1e-5);
        float s = gamma[tid] * (float)inv;
        sc[tid] = s;
        sh[tid] = beta[tid] - (float)m * s;
    }
    __syncthreads();
    long total  = (long)NV * NPL;
    long stride = (long)gridDim.x * blockDim.x;
    for (long id = blockIdx.x * (long)blockDim.x + tid; id < total; id += stride) {
        int vox = (int)(id % NV);
        int pl  = (int)(id / NV);
        const float4* src = (const float4*)&fout[(long)vox * C + pl * 16];
        float4 v0 = src[0], v1 = src[1], v2 = src[2], v3 = src[3];
        float vv[16] = {v0.x, v0.y, v0.z, v0.w, v1.x, v1.y, v1.z, v1.w,
                        v2.x, v2.y, v2.z, v2.w, v3.x, v3.y, v3.z, v3.w};
        unsigned p[8];
#pragma unroll
        for (int q = 0; q < 8; q++) {
            float r0 = vv[2*q]   * sc[pl*16 + 2*q]   + sh[pl*16 + 2*q];
            float r1 = vv[2*q+1] * sc[pl*16 + 2*q+1] + sh[pl*16 + 2*q+1];
            r0 = fmaxf(r0, LRELU * r0);
            r1 = fmaxf(r1, LRELU * r1);
            p[q] = packh2(r0, r1);
        }
        uint4* dst = (uint4*)&act[((long)pl * NV + vox) * 8];
        dst[0] = make_uint4(p[0], p[1], p[2], p[3]);
        dst[1] = make_uint4(p[4], p[5], p[6], p[7]);
    }
}

// ---------------- fused BN + leaky relu + projection (layer 3) ----------------
__global__ void bnproj_kernel(const float* __restrict__ fout, const double* __restrict__ sum,
                              const double* __restrict__ ssq, const float* __restrict__ gamma,
                              const float* __restrict__ beta, const float* __restrict__ wp,
                              const float* __restrict__ bp, float* __restrict__ out) {
    __shared__ float sc[H], sh[H], sw[H];
    __shared__ float sb;
    int tid = threadIdx.x;
    if (tid < H) {
        double m   = sum[tid] / (double)NV;
        double var = ssq[tid] / (double)NV - m * m;
        double inv = 1.0 / sqrt(var + 1e-5);
        float s = gamma[tid] * (float)inv;
        sc[tid] = s;
        sh[tid] = beta[tid] - (float)m * s;
        sw[tid] = wp[tid];
    }
    if (tid == 0) sb = bp[0];
    __syncthreads();
    int v = blockIdx.x * blockDim.x + tid;
    if (v >= NV) return;
    const float4* src = (const float4*)&fout[(long)v * H];
    float4 v0 = src[0], v1 = src[1], v2 = src[2], v3 = src[3];
    float vv[16] = {v0.x, v0.y, v0.z, v0.w, v1.x, v1.y, v1.z, v1.w,
                    v2.x, v2.y, v2.z, v2.w, v3.x, v3.y, v3.z, v3.w};
    float a = sb;
#pragma unroll
    for (int c = 0; c < H; c++) {
        float r = vv[c] * sc[c] + sh[c];
        r = fmaxf(r, LRELU * r);
        a += r * sw[c];
    }
    out[v] = a;
}

// ---------------- launch ----------------
extern "C" void kernel_launch(void* const* d_in, const int* in_sizes, int n_in,
                              void* d_out, int out_size) {
    const float* x      = (const float*)d_in[0];
    const float* w_emb  = (const float*)d_in[1];
    const float* b_emb  = (const float*)d_in[2];
    const float* W1     = (const float*)d_in[3];
    const float* b1     = (const float*)d_in[4];
    const float* g1     = (const float*)d_in[5];
    const float* be1    = (const float*)d_in[6];
    const float* W2     = (const float*)d_in[7];
    const float* b2     = (const float*)d_in[8];
    const float* g2     = (const float*)d_in[9];
    const float* be2    = (const float*)d_in[10];
    const float* W3     = (const float*)d_in[11];
    const float* b3     = (const float*)d_in[12];
    const float* g3     = (const float*)d_in[13];
    const float* be3    = (const float*)d_in[14];
    const float* w_proj = (const float*)d_in[15];
    const float* b_proj = (const float*)d_in[16];

    unsigned *actA, *actB, *actC, *wx1, *wx2, *wx3;
    float* fout;
    double *sums, *ssqs;
    cudaGetSymbolAddress((void**)&actA, g_actA);
    cudaGetSymbolAddress((void**)&actB, g_actB);
    cudaGetSymbolAddress((void**)&actC, g_actC);
    cudaGetSymbolAddress((void**)&fout, g_fout);
    cudaGetSymbolAddress((void**)&wx1, g_wx1);
    cudaGetSymbolAddress((void**)&wx2, g_wx2);
    cudaGetSymbolAddress((void**)&wx3, g_wx3);
    cudaGetSymbolAddress((void**)&sums, g_sum);
    cudaGetSymbolAddress((void**)&ssqs, g_ssq);

    cudaFuncSetAttribute(conv_mma_kernel<16, 25>, cudaFuncAttributeMaxDynamicSharedMemorySize, 34944);
    cudaFuncSetAttribute(conv_mma_kernel<32, 25>, cudaFuncAttributeMaxDynamicSharedMemorySize, 49152);
    cudaFuncSetAttribute(conv_mma_kernel<16, 50>, cudaFuncAttributeMaxDynamicSharedMemorySize, 34944);

    // position 0
    embed_kernel<<<NV / 256, 256>>>(x, w_emb, b_emb, actA);
    // position 1
    wext_all_kernel<<<(440000 + 255) / 256, 256>>>(W1, W2, W3, wx1, wx2, wx3);
    // position 2
    zero_stats_kernel<<<1, 128>>>(sums, ssqs);
    // position 3: conv1  (ncu capture slot)
    conv_mma_kernel<16, 25><<<1024, 128, 34944>>>(actA, wx1, b1, fout, sums + 0, ssqs + 0);
    bn_apply_kernel<16><<<1024, 256>>>(fout, sums + 0, ssqs + 0, g1, be1, actB);

    conv_mma_kernel<32, 25><<<1024, 128, 49152>>>(actB, wx2, b2, fout, sums + 32, ssqs + 32);
    bn_apply_kernel<32><<<2048, 256>>>(fout, sums + 32, ssqs + 32, g2, be2, actC);

    conv_mma_kernel<16, 50><<<1024, 128, 34944>>>(actC, wx3, b3, fout, sums + 64, ssqs + 64);
    bnproj_kernel<<<NV / 256, 256>>>(fout, sums + 64, ssqs + 64, g3, be3, w_proj, b_proj, (float*)d_out);
}